// round 3
// baseline (speedup 1.0000x reference)
#include <cuda_runtime.h>
#include <mma.h>
#include <cstdint>

using namespace nvcuda;

#define BS   4
#define TN   512
#define DM   512
#define HN   8
#define HDN  64
#define LN_  6
#define VN   50257
#define EPSV 1e-5f

// ---------------- scratch (static device arrays; no allocation) ----------------
__device__ float g_h   [BS*TN*DM];
__device__ float g_tmp [BS*TN*DM];
__device__ float g_qkv [BS*TN*3*DM];
__device__ float g_sc  [BS*HN*TN*TN];
__device__ float g_ff  [BS*TN*4*DM];
__device__ float g_att [BS*TN*DM];

// ---------------- embedding ----------------
__global__ void embed_k(const int* __restrict__ x, const float* __restrict__ tok,
                        const float* __restrict__ pos, float* __restrict__ h) {
    int i = blockIdx.x * 256 + threadIdx.x;
    if (i >= BS*TN*DM) return;
    int d  = i % DM;
    int bt = i / DM;
    int t  = bt % TN;
    h[i] = tok[(size_t)x[bt] * DM + d] + pos[t * DM + d];
}

// ---------------- layernorm ----------------
__global__ __launch_bounds__(256) void ln_k(const float* __restrict__ in, float* __restrict__ out,
                                            const float* __restrict__ sc, const float* __restrict__ bi) {
    __shared__ float s1[256], s2[256];
    int row = blockIdx.x;
    int tid = threadIdx.x;
    const float* xr = in + (size_t)row * DM;
    float a = xr[tid], b = xr[tid + 256];
    s1[tid] = a + b;
    s2[tid] = a * a + b * b;
    __syncthreads();
    for (int s = 128; s > 0; s >>= 1) {
        if (tid < s) { s1[tid] += s1[tid + s]; s2[tid] += s2[tid + s]; }
        __syncthreads();
    }
    float mean = s1[0] * (1.0f / DM);
    float var  = s2[0] * (1.0f / DM) - mean * mean;
    float r    = rsqrtf(var + EPSV);
    out[(size_t)row * DM + tid]       = (a - mean) * r * sc[tid]       + bi[tid];
    out[(size_t)row * DM + tid + 256] = (b - mean) * r * sc[tid + 256] + bi[tid + 256];
}

// ---------------- TF32 wmma GEMM, double-buffered ----------------
// C = A[MxK] @ B[KxN] + bias (+epilogue)
// MODE 0: bias; MODE 1: bias + exact gelu; MODE 2: bias + residual
// VECB: float4 B loads (requires N % 4 == 0). Head GEMM (N=50257) uses scalar.
template <int BM, int BN, int WR, int WC, int MODE, bool VECB>
__global__ __launch_bounds__(256) void gemm2(const float* __restrict__ A,
                                             const float* __restrict__ B,
                                             const float* __restrict__ bias,
                                             const float* __restrict__ res,
                                             float* __restrict__ C,
                                             int M, int N, int K) {
    constexpr int BK  = 16;
    constexpr int FM  = BM / (WR * 16);
    constexpr int FN  = BN / (WC * 16);
    constexpr int LDA = 24;          // 96B rows: 16B-aligned fragment bases
    constexpr int LDB = BN + 4;
    constexpr int IA  = (BM * 4) / 256;   // float4 loads per thread for A stage
    constexpr int IB  = (BN * 4) / 256;   // float4 loads per thread for B stage
    constexpr int WTM = BM / WR;
    constexpr int WTN = BN / WC;

    __shared__ union SMU {
        struct { float A[2][BM][LDA]; float B[2][BK][LDB]; } st;
        float epi[8][16][24];
    } sm;

    const int tid  = threadIdx.x;
    const int warp = tid >> 5;
    const int lane = tid & 31;
    const int wm   = warp / WC;
    const int wn   = warp % WC;
    const int m0   = blockIdx.y * BM;
    const int n0   = blockIdx.x * BN;

    wmma::fragment<wmma::accumulator, 16, 16, 8, float> acc[FM][FN];
    #pragma unroll
    for (int i = 0; i < FM; i++)
        #pragma unroll
        for (int j = 0; j < FN; j++)
            wmma::fill_fragment(acc[i][j], 0.0f);

    // per-thread load coordinates
    int rA[IA], cA[IA];
    #pragma unroll
    for (int it = 0; it < IA; it++) {
        int idx = tid + it * 256;
        rA[it] = idx >> 2;
        cA[it] = (idx & 3) * 4;
    }
    int rB[IB], cB[IB];
    #pragma unroll
    for (int it = 0; it < IB; it++) {
        int idx = tid + it * 256;
        rB[it] = idx / (BN / 4);
        cB[it] = (idx % (BN / 4)) * 4;
    }

    // B tile loader (global -> float4), handles tail + non-vectorizable N
    auto ldB = [&](int krow, int cbase) -> float4 {
        const float* bp = &B[(size_t)krow * N];
        if (VECB) {
            if (n0 + BN <= N)
                return *(const float4*)&bp[n0 + cbase];
        }
        float4 v;
        int base = n0 + cbase;
        v.x = (base + 0 < N) ? bp[base + 0] : 0.0f;
        v.y = (base + 1 < N) ? bp[base + 1] : 0.0f;
        v.z = (base + 2 < N) ? bp[base + 2] : 0.0f;
        v.w = (base + 3 < N) ? bp[base + 3] : 0.0f;
        return v;
    };

    // prologue: stage 0 straight into smem
    #pragma unroll
    for (int it = 0; it < IA; it++)
        *(float4*)&sm.st.A[0][rA[it]][cA[it]] =
            *(const float4*)&A[(size_t)(m0 + rA[it]) * K + cA[it]];
    #pragma unroll
    for (int it = 0; it < IB; it++)
        *(float4*)&sm.st.B[0][rB[it]][cB[it]] = ldB(rB[it], cB[it]);
    __syncthreads();

    const int nst = K / BK;
    float4 pA[IA], pB[IB];

    for (int s = 0; s < nst; s++) {
        const int cur = s & 1;
        const bool hasNext = (s + 1 < nst);

        if (hasNext) {
            const int k0 = (s + 1) * BK;
            #pragma unroll
            for (int it = 0; it < IA; it++)
                pA[it] = *(const float4*)&A[(size_t)(m0 + rA[it]) * K + k0 + cA[it]];
            #pragma unroll
            for (int it = 0; it < IB; it++)
                pB[it] = ldB(k0 + rB[it], cB[it]);
        }

        // compute current stage
        #pragma unroll
        for (int ks = 0; ks < BK; ks += 8) {
            wmma::fragment<wmma::matrix_a, 16, 16, 8, wmma::precision::tf32, wmma::row_major> af[FM];
            wmma::fragment<wmma::matrix_b, 16, 16, 8, wmma::precision::tf32, wmma::row_major> bf[FN];
            #pragma unroll
            for (int i = 0; i < FM; i++) {
                wmma::load_matrix_sync(af[i], &sm.st.A[cur][wm * WTM + i * 16][ks], LDA);
                #pragma unroll
                for (int t = 0; t < af[i].num_elements; t++)
                    af[i].x[t] = wmma::__float_to_tf32(af[i].x[t]);
            }
            #pragma unroll
            for (int j = 0; j < FN; j++) {
                wmma::load_matrix_sync(bf[j], &sm.st.B[cur][ks][wn * WTN + j * 16], LDB);
                #pragma unroll
                for (int t = 0; t < bf[j].num_elements; t++)
                    bf[j].x[t] = wmma::__float_to_tf32(bf[j].x[t]);
            }
            #pragma unroll
            for (int i = 0; i < FM; i++)
                #pragma unroll
                for (int j = 0; j < FN; j++)
                    wmma::mma_sync(acc[i][j], af[i], bf[j], acc[i][j]);
        }

        if (hasNext) {
            const int nb = cur ^ 1;
            #pragma unroll
            for (int it = 0; it < IA; it++)
                *(float4*)&sm.st.A[nb][rA[it]][cA[it]] = pA[it];
            #pragma unroll
            for (int it = 0; it < IB; it++)
                *(float4*)&sm.st.B[nb][rB[it]][cB[it]] = pB[it];
        }
        __syncthreads();
    }

    // fused epilogue via per-warp private smem patch
    float* patch = &sm.epi[warp][0][0];
    #pragma unroll
    for (int i = 0; i < FM; i++)
        #pragma unroll
        for (int j = 0; j < FN; j++) {
            wmma::store_matrix_sync(patch, acc[i][j], 24, wmma::mem_row_major);
            __syncwarp();
            const int rg0 = m0 + wm * WTM + i * 16;
            const int cg0 = n0 + wn * WTN + j * 16;
            #pragma unroll
            for (int e = 0; e < 8; e++) {
                int li  = lane * 8 + e;
                int r   = li >> 4;
                int c   = li & 15;
                int col = cg0 + c;
                if (col < N) {
                    size_t gi = (size_t)(rg0 + r) * N + col;
                    float v = patch[r * 24 + c] + bias[col];
                    if (MODE == 1) v = 0.5f * v * (1.0f + erff(v * 0.70710678118654752f));
                    if (MODE == 2) v += res[gi];
                    C[gi] = v;
                }
            }
            __syncwarp();
        }
}

// ---------------- attention: S = Q K^T * scale with causal mask ----------------
__global__ __launch_bounds__(256) void scores_k(const float* __restrict__ qkv, float* __restrict__ sc) {
    int bh = blockIdx.z;
    int b  = bh >> 3;
    int h  = bh & 7;
    int q0 = blockIdx.y << 6;
    int j0 = blockIdx.x << 6;
    float* out = sc + (size_t)bh * TN * TN;
    int tid = threadIdx.x;

    if (j0 > q0) {
        #pragma unroll
        for (int r = 0; r < 16; r++) {
            int idx = r * 256 + tid;
            out[(size_t)(q0 + (idx >> 6)) * TN + j0 + (idx & 63)] = -1e30f;
        }
        return;
    }

    __shared__ float Qs[64][65], Ks[64][65];
    #pragma unroll
    for (int r = 0; r < 16; r++) {
        int idx = r * 256 + tid;
        int rr = idx >> 6, cc = idx & 63;
        Qs[rr][cc] = qkv[((size_t)(b * TN + q0 + rr)) * 1536 + h * 64 + cc];
        Ks[rr][cc] = qkv[((size_t)(b * TN + j0 + rr)) * 1536 + 512 + h * 64 + cc];
    }
    __syncthreads();

    int tx = tid & 15, ty = tid >> 4;
    float acc[4][4] = {};
    #pragma unroll 8
    for (int d = 0; d < 64; d++) {
        float a0 = Qs[ty * 4 + 0][d], a1 = Qs[ty * 4 + 1][d], a2 = Qs[ty * 4 + 2][d], a3 = Qs[ty * 4 + 3][d];
        float b0 = Ks[tx * 4 + 0][d], b1 = Ks[tx * 4 + 1][d], b2 = Ks[tx * 4 + 2][d], b3 = Ks[tx * 4 + 3][d];
        acc[0][0] += a0 * b0; acc[0][1] += a0 * b1; acc[0][2] += a0 * b2; acc[0][3] += a0 * b3;
        acc[1][0] += a1 * b0; acc[1][1] += a1 * b1; acc[1][2] += a1 * b2; acc[1][3] += a1 * b3;
        acc[2][0] += a2 * b0; acc[2][1] += a2 * b1; acc[2][2] += a2 * b2; acc[2][3] += a2 * b3;
        acc[3][0] += a3 * b0; acc[3][1] += a3 * b1; acc[3][2] += a3 * b2; acc[3][3] += a3 * b3;
    }
    #pragma unroll
    for (int i = 0; i < 4; i++)
        #pragma unroll
        for (int j = 0; j < 4; j++) {
            int row = q0 + ty * 4 + i;
            int col = j0 + tx * 4 + j;
            out[(size_t)row * TN + col] = (col <= row) ? acc[i][j] * 0.125f : -1e30f;
        }
}

// ---------------- softmax ----------------
__global__ __launch_bounds__(256) void softmax_k(float* __restrict__ sc) {
    int warp = threadIdx.x >> 5, lane = threadIdx.x & 31;
    size_t row = (size_t)blockIdx.x * 8 + warp;
    float* p = sc + row * TN;
    float v[16];
    float mx = -3.4e38f;
    #pragma unroll
    for (int i = 0; i < 16; i++) { v[i] = p[lane + 32 * i]; mx = fmaxf(mx, v[i]); }
    #pragma unroll
    for (int o = 16; o; o >>= 1) mx = fmaxf(mx, __shfl_xor_sync(0xffffffffu, mx, o));
    float s = 0.0f;
    #pragma unroll
    for (int i = 0; i < 16; i++) { v[i] = expf(v[i] - mx); s += v[i]; }
    #pragma unroll
    for (int o = 16; o; o >>= 1) s += __shfl_xor_sync(0xffffffffu, s, o);
    float inv = 1.0f / s;
    #pragma unroll
    for (int i = 0; i < 16; i++) p[lane + 32 * i] = v[i] * inv;
}

// ---------------- O = P @ V ----------------
__global__ __launch_bounds__(256) void av_k(const float* __restrict__ sc, const float* __restrict__ qkv,
                                            float* __restrict__ o) {
    int bh = blockIdx.z;
    int b  = bh >> 3;
    int h  = bh & 7;
    int q0 = blockIdx.y << 6;
    const float* P = sc + (size_t)bh * TN * TN;

    __shared__ float Ps[64][65], Vs[64][65];
    int tid = threadIdx.x;
    int tx = tid & 15, ty = tid >> 4;
    float acc[4][4] = {};

    for (int k0 = 0; k0 <= q0; k0 += 64) {
        #pragma unroll
        for (int r = 0; r < 16; r++) {
            int idx = r * 256 + tid;
            int rr = idx >> 6, cc = idx & 63;
            Ps[rr][cc] = P[(size_t)(q0 + rr) * TN + k0 + cc];
            Vs[rr][cc] = qkv[((size_t)(b * TN + k0 + rr)) * 1536 + 1024 + h * 64 + cc];
        }
        __syncthreads();
        #pragma unroll 8
        for (int kk = 0; kk < 64; kk++) {
            float a0 = Ps[ty * 4 + 0][kk], a1 = Ps[ty * 4 + 1][kk], a2 = Ps[ty * 4 + 2][kk], a3 = Ps[ty * 4 + 3][kk];
            float b0 = Vs[kk][tx * 4 + 0], b1 = Vs[kk][tx * 4 + 1], b2 = Vs[kk][tx * 4 + 2], b3 = Vs[kk][tx * 4 + 3];
            acc[0][0] += a0 * b0; acc[0][1] += a0 * b1; acc[0][2] += a0 * b2; acc[0][3] += a0 * b3;
            acc[1][0] += a1 * b0; acc[1][1] += a1 * b1; acc[1][2] += a1 * b2; acc[1][3] += a1 * b3;
            acc[2][0] += a2 * b0; acc[2][1] += a2 * b1; acc[2][2] += a2 * b2; acc[2][3] += a2 * b3;
            acc[3][0] += a3 * b0; acc[3][1] += a3 * b1; acc[3][2] += a3 * b2; acc[3][3] += a3 * b3;
        }
        __syncthreads();
    }
    #pragma unroll
    for (int i = 0; i < 4; i++)
        #pragma unroll
        for (int j = 0; j < 4; j++)
            o[((size_t)(b * TN + q0 + ty * 4 + i)) * DM + h * 64 + tx * 4 + j] = acc[i][j];
}

// ---------------- launch ----------------
extern "C" void kernel_launch(void* const* d_in, const int* in_sizes, int n_in,
                              void* d_out, int out_size) {
    const int*   x      = (const int*)  d_in[0];
    const float* tok    = (const float*)d_in[1];
    const float* pos    = (const float*)d_in[2];
    const float* qkv_w  = (const float*)d_in[3];
    const float* qkv_b  = (const float*)d_in[4];
    const float* out_w  = (const float*)d_in[5];
    const float* out_b  = (const float*)d_in[6];
    const float* ln1_s  = (const float*)d_in[7];
    const float* ln1_b  = (const float*)d_in[8];
    const float* ff1_w  = (const float*)d_in[9];
    const float* ff1_b  = (const float*)d_in[10];
    const float* ff2_w  = (const float*)d_in[11];
    const float* ff2_b  = (const float*)d_in[12];
    const float* ln2_s  = (const float*)d_in[13];
    const float* ln2_b  = (const float*)d_in[14];
    const float* lnf_s  = (const float*)d_in[15];
    const float* lnf_b  = (const float*)d_in[16];
    const float* head_w = (const float*)d_in[17];
    const float* head_b = (const float*)d_in[18];
    float* out = (float*)d_out;

    float *h, *tmp, *qkv, *sc, *ff, *att;
    cudaGetSymbolAddress((void**)&h,   g_h);
    cudaGetSymbolAddress((void**)&tmp, g_tmp);
    cudaGetSymbolAddress((void**)&qkv, g_qkv);
    cudaGetSymbolAddress((void**)&sc,  g_sc);
    cudaGetSymbolAddress((void**)&ff,  g_ff);
    cudaGetSymbolAddress((void**)&att, g_att);

    const int M = BS * TN;  // 2048

    embed_k<<<(BS*TN*DM + 255) / 256, 256>>>(x, tok, pos, h);

    for (int l = 0; l < LN_; l++) {
        const float* w_qkv = qkv_w + (size_t)l * DM * 3 * DM;
        const float* b_qkv = qkv_b + (size_t)l * 3 * DM;
        const float* w_out = out_w + (size_t)l * DM * DM;
        const float* b_out = out_b + (size_t)l * DM;
        const float* w_f1  = ff1_w + (size_t)l * DM * 4 * DM;
        const float* b_f1  = ff1_b + (size_t)l * 4 * DM;
        const float* w_f2  = ff2_w + (size_t)l * 4 * DM * DM;
        const float* b_f2  = ff2_b + (size_t)l * DM;

        // attention block
        ln_k<<<M, 256>>>(h, tmp, ln1_s + l * DM, ln1_b + l * DM);
        gemm2<128,128,2,4,0,true><<<dim3(12, 16), 256>>>(tmp, w_qkv, b_qkv, nullptr, qkv, M, 3*DM, DM);
        scores_k<<<dim3(8, 8, 32), 256>>>(qkv, sc);
        softmax_k<<<(BS * HN * TN) / 8, 256>>>(sc);
        av_k<<<dim3(1, 8, 32), 256>>>(sc, qkv, att);
        gemm2<64,64,4,2,2,true><<<dim3(8, 32), 256>>>(att, w_out, b_out, h, h, M, DM, DM);

        // feed-forward block
        ln_k<<<M, 256>>>(h, tmp, ln2_s + l * DM, ln2_b + l * DM);
        gemm2<128,128,2,4,1,true><<<dim3(16, 16), 256>>>(tmp, w_f1, b_f1, nullptr, ff, M, 4*DM, DM);
        gemm2<64,64,4,2,2,true><<<dim3(8, 32), 256>>>(ff, w_f2, b_f2, h, h, M, DM, 4*DM);
    }

    // final LN + LM head (N = 50257 odd -> scalar B loads)
    ln_k<<<M, 256>>>(h, tmp, lnf_s, lnf_b);
    gemm2<128,128,2,4,0,false><<<dim3((VN + 127) / 128, 16), 256>>>(tmp, head_w, head_b, nullptr, out, M, VN, DM);
}

// round 4
// speedup vs baseline: 1.2378x; 1.2378x over previous
#include <cuda_runtime.h>
#include <mma.h>
#include <cstdint>

using namespace nvcuda;

#define BS   4
#define TN   512
#define DM   512
#define HN   8
#define HDN  64
#define LN_  6
#define VN   50257
#define EPSV 1e-5f

// ---------------- scratch (static device arrays; no allocation) ----------------
__device__ float g_h   [BS*TN*DM];
__device__ float g_tmp [BS*TN*DM];
__device__ float g_qkv [BS*TN*3*DM];
__device__ float g_sc  [BS*HN*TN*TN];
__device__ float g_ff  [BS*TN*4*DM];
__device__ float g_att [BS*TN*DM];

// ---------------- embedding ----------------
__global__ void embed_k(const int* __restrict__ x, const float* __restrict__ tok,
                        const float* __restrict__ pos, float* __restrict__ h) {
    int i = blockIdx.x * 256 + threadIdx.x;
    if (i >= BS*TN*DM) return;
    int d  = i % DM;
    int bt = i / DM;
    int t  = bt % TN;
    h[i] = tok[(size_t)x[bt] * DM + d] + pos[t * DM + d];
}

// ---------------- layernorm ----------------
__global__ __launch_bounds__(256) void ln_k(const float* __restrict__ in, float* __restrict__ out,
                                            const float* __restrict__ sc, const float* __restrict__ bi) {
    __shared__ float s1[256], s2[256];
    int row = blockIdx.x;
    int tid = threadIdx.x;
    const float* xr = in + (size_t)row * DM;
    float a = xr[tid], b = xr[tid + 256];
    s1[tid] = a + b;
    s2[tid] = a * a + b * b;
    __syncthreads();
    for (int s = 128; s > 0; s >>= 1) {
        if (tid < s) { s1[tid] += s1[tid + s]; s2[tid] += s2[tid + s]; }
        __syncthreads();
    }
    float mean = s1[0] * (1.0f / DM);
    float var  = s2[0] * (1.0f / DM) - mean * mean;
    float r    = rsqrtf(var + EPSV);
    out[(size_t)row * DM + tid]       = (a - mean) * r * sc[tid]       + bi[tid];
    out[(size_t)row * DM + tid + 256] = (b - mean) * r * sc[tid + 256] + bi[tid + 256];
}

// ---------------- TF32 wmma GEMM, cp.async 3-stage pipeline ----------------
// C = A[MxK] @ B[KxN] + bias (+epilogue)
// MODE 0: bias; MODE 1: bias + exact gelu; MODE 2: bias + residual
// VECB: 16B cp.async for B (requires BN-aligned full tiles in N). Head uses 4B+zfill.
// Warp tile is always 32x32 (FM=FN=2) -> only 32 accumulator regs/thread.
template <int BM, int BN, int NT, int WR, int WC, int MODE, bool VECB>
__global__ __launch_bounds__(NT) void gemm3(const float* __restrict__ A,
                                            const float* __restrict__ B,
                                            const float* __restrict__ bias,
                                            const float* __restrict__ res,
                                            float* __restrict__ C,
                                            int M, int N, int K) {
    constexpr int BK  = 16;
    constexpr int ST  = 3;
    constexpr int LDA = 20;
    constexpr int LDB = BN + 4;
    constexpr int NW  = NT / 32;
    constexpr int FM  = BM / (WR * 16);
    constexpr int FN  = BN / (WC * 16);
    constexpr int IA  = (BM * BK / 4) / NT;   // 16B cp.async per thread for A
    constexpr int IBV = (BK * BN / 4) / NT;   // 16B cp.async per thread for B
    constexpr int IBS = (BK * BN) / NT;       // 4B  cp.async per thread for B (head)

    __shared__ union SMU {
        struct { float A[ST][BM][LDA]; float B[ST][BK][LDB]; } p;
        float epi[NW][16][20];
    } sm;

    const int tid  = threadIdx.x;
    const int warp = tid >> 5;
    const int lane = tid & 31;
    const int wm   = warp / WC;
    const int wn   = warp % WC;
    const int m0   = blockIdx.y * BM;
    const int n0   = blockIdx.x * BN;

    const uint32_t sA0 = (uint32_t)__cvta_generic_to_shared(&sm.p.A[0][0][0]);
    const uint32_t sB0 = (uint32_t)__cvta_generic_to_shared(&sm.p.B[0][0][0]);

    wmma::fragment<wmma::accumulator, 16, 16, 8, float> acc[FM][FN];
    #pragma unroll
    for (int i = 0; i < FM; i++)
        #pragma unroll
        for (int j = 0; j < FN; j++)
            wmma::fill_fragment(acc[i][j], 0.0f);

    // issue one pipeline stage of cp.async (A tile + B tile)
    auto issue = [&](int stage, int k0) {
        const int buf = stage % ST;
        #pragma unroll
        for (int i = 0; i < IA; i++) {
            int idx = tid + i * NT;
            int r   = idx / (BK / 4);
            int c   = (idx % (BK / 4)) * 4;
            uint32_t dst = sA0 + (((buf * BM + r) * LDA + c) << 2);
            const float* src = A + (size_t)(m0 + r) * K + k0 + c;
            asm volatile("cp.async.ca.shared.global [%0], [%1], 16;" :: "r"(dst), "l"(src));
        }
        if (VECB) {
            #pragma unroll
            for (int i = 0; i < IBV; i++) {
                int idx = tid + i * NT;
                int r   = idx / (BN / 4);
                int c   = (idx % (BN / 4)) * 4;
                uint32_t dst = sB0 + (((buf * BK + r) * LDB + c) << 2);
                const float* src = B + (size_t)(k0 + r) * N + n0 + c;
                asm volatile("cp.async.ca.shared.global [%0], [%1], 16;" :: "r"(dst), "l"(src));
            }
        } else {
            #pragma unroll
            for (int i = 0; i < IBS; i++) {
                int idx = tid + i * NT;
                int r   = idx / BN;
                int c   = idx % BN;
                uint32_t dst = sB0 + (((buf * BK + r) * LDB + c) << 2);
                int gc  = n0 + c;
                int ok  = (gc < N);
                const float* src = B + (size_t)(k0 + r) * N + (ok ? gc : 0);
                int sz = ok ? 4 : 0;
                asm volatile("cp.async.ca.shared.global [%0], [%1], 4, %2;" :: "r"(dst), "l"(src), "r"(sz));
            }
        }
    };

    const int nst = K / BK;

    issue(0, 0);
    asm volatile("cp.async.commit_group;" ::: "memory");
    issue(1, BK);
    asm volatile("cp.async.commit_group;" ::: "memory");

    for (int s = 0; s < nst; s++) {
        asm volatile("cp.async.wait_group 1;" ::: "memory");
        __syncthreads();

        if (s + 2 < nst) issue(s + 2, (s + 2) * BK);
        asm volatile("cp.async.commit_group;" ::: "memory");

        const int buf = s % ST;
        #pragma unroll
        for (int ks = 0; ks < BK; ks += 8) {
            wmma::fragment<wmma::matrix_a, 16, 16, 8, wmma::precision::tf32, wmma::row_major> af[FM];
            wmma::fragment<wmma::matrix_b, 16, 16, 8, wmma::precision::tf32, wmma::row_major> bf[FN];
            #pragma unroll
            for (int i = 0; i < FM; i++) {
                wmma::load_matrix_sync(af[i], &sm.p.A[buf][wm * (BM / WR) + i * 16][ks], LDA);
                #pragma unroll
                for (int t = 0; t < af[i].num_elements; t++)
                    af[i].x[t] = wmma::__float_to_tf32(af[i].x[t]);
            }
            #pragma unroll
            for (int j = 0; j < FN; j++) {
                wmma::load_matrix_sync(bf[j], &sm.p.B[buf][ks][wn * (BN / WC) + j * 16], LDB);
                #pragma unroll
                for (int t = 0; t < bf[j].num_elements; t++)
                    bf[j].x[t] = wmma::__float_to_tf32(bf[j].x[t]);
            }
            #pragma unroll
            for (int i = 0; i < FM; i++)
                #pragma unroll
                for (int j = 0; j < FN; j++)
                    wmma::mma_sync(acc[i][j], af[i], bf[j], acc[i][j]);
        }
    }

    __syncthreads();   // pipeline smem dead; epilogue aliases it

    // fused epilogue via per-warp private smem patch
    float* patch = &sm.epi[warp][0][0];
    #pragma unroll
    for (int i = 0; i < FM; i++)
        #pragma unroll
        for (int j = 0; j < FN; j++) {
            wmma::store_matrix_sync(patch, acc[i][j], 20, wmma::mem_row_major);
            __syncwarp();
            const int rg0 = m0 + wm * (BM / WR) + i * 16;
            const int cg0 = n0 + wn * (BN / WC) + j * 16;
            #pragma unroll
            for (int e = 0; e < 8; e++) {
                int li  = lane * 8 + e;
                int r   = li >> 4;
                int c   = li & 15;
                int col = cg0 + c;
                if (col < N) {
                    size_t gi = (size_t)(rg0 + r) * N + col;
                    float v = patch[r * 20 + c] + bias[col];
                    if (MODE == 1) v = 0.5f * v * (1.0f + erff(v * 0.70710678118654752f));
                    if (MODE == 2) v += res[gi];
                    C[gi] = v;
                }
            }
            __syncwarp();
        }
}

// ---------------- attention: S = Q K^T * scale with causal mask ----------------
__global__ __launch_bounds__(256) void scores_k(const float* __restrict__ qkv, float* __restrict__ sc) {
    int bh = blockIdx.z;
    int b  = bh >> 3;
    int h  = bh & 7;
    int q0 = blockIdx.y << 6;
    int j0 = blockIdx.x << 6;
    float* out = sc + (size_t)bh * TN * TN;
    int tid = threadIdx.x;

    if (j0 > q0) {
        #pragma unroll
        for (int r = 0; r < 16; r++) {
            int idx = r * 256 + tid;
            out[(size_t)(q0 + (idx >> 6)) * TN + j0 + (idx & 63)] = -1e30f;
        }
        return;
    }

    __shared__ float Qs[64][65], Ks[64][65];
    #pragma unroll
    for (int r = 0; r < 16; r++) {
        int idx = r * 256 + tid;
        int rr = idx >> 6, cc = idx & 63;
        Qs[rr][cc] = qkv[((size_t)(b * TN + q0 + rr)) * 1536 + h * 64 + cc];
        Ks[rr][cc] = qkv[((size_t)(b * TN + j0 + rr)) * 1536 + 512 + h * 64 + cc];
    }
    __syncthreads();

    int tx = tid & 15, ty = tid >> 4;
    float acc[4][4] = {};
    #pragma unroll 8
    for (int d = 0; d < 64; d++) {
        float a0 = Qs[ty * 4 + 0][d], a1 = Qs[ty * 4 + 1][d], a2 = Qs[ty * 4 + 2][d], a3 = Qs[ty * 4 + 3][d];
        float b0 = Ks[tx * 4 + 0][d], b1 = Ks[tx * 4 + 1][d], b2 = Ks[tx * 4 + 2][d], b3 = Ks[tx * 4 + 3][d];
        acc[0][0] += a0 * b0; acc[0][1] += a0 * b1; acc[0][2] += a0 * b2; acc[0][3] += a0 * b3;
        acc[1][0] += a1 * b0; acc[1][1] += a1 * b1; acc[1][2] += a1 * b2; acc[1][3] += a1 * b3;
        acc[2][0] += a2 * b0; acc[2][1] += a2 * b1; acc[2][2] += a2 * b2; acc[2][3] += a2 * b3;
        acc[3][0] += a3 * b0; acc[3][1] += a3 * b1; acc[3][2] += a3 * b2; acc[3][3] += a3 * b3;
    }
    #pragma unroll
    for (int i = 0; i < 4; i++)
        #pragma unroll
        for (int j = 0; j < 4; j++) {
            int row = q0 + ty * 4 + i;
            int col = j0 + tx * 4 + j;
            out[(size_t)row * TN + col] = (col <= row) ? acc[i][j] * 0.125f : -1e30f;
        }
}

// ---------------- softmax ----------------
__global__ __launch_bounds__(256) void softmax_k(float* __restrict__ sc) {
    int warp = threadIdx.x >> 5, lane = threadIdx.x & 31;
    size_t row = (size_t)blockIdx.x * 8 + warp;
    float* p = sc + row * TN;
    float v[16];
    float mx = -3.4e38f;
    #pragma unroll
    for (int i = 0; i < 16; i++) { v[i] = p[lane + 32 * i]; mx = fmaxf(mx, v[i]); }
    #pragma unroll
    for (int o = 16; o; o >>= 1) mx = fmaxf(mx, __shfl_xor_sync(0xffffffffu, mx, o));
    float s = 0.0f;
    #pragma unroll
    for (int i = 0; i < 16; i++) { v[i] = expf(v[i] - mx); s += v[i]; }
    #pragma unroll
    for (int o = 16; o; o >>= 1) s += __shfl_xor_sync(0xffffffffu, s, o);
    float inv = 1.0f / s;
    #pragma unroll
    for (int i = 0; i < 16; i++) p[lane + 32 * i] = v[i] * inv;
}

// ---------------- O = P @ V ----------------
__global__ __launch_bounds__(256) void av_k(const float* __restrict__ sc, const float* __restrict__ qkv,
                                            float* __restrict__ o) {
    int bh = blockIdx.z;
    int b  = bh >> 3;
    int h  = bh & 7;
    int q0 = blockIdx.y << 6;
    const float* P = sc + (size_t)bh * TN * TN;

    __shared__ float Ps[64][65], Vs[64][65];
    int tid = threadIdx.x;
    int tx = tid & 15, ty = tid >> 4;
    float acc[4][4] = {};

    for (int k0 = 0; k0 <= q0; k0 += 64) {
        #pragma unroll
        for (int r = 0; r < 16; r++) {
            int idx = r * 256 + tid;
            int rr = idx >> 6, cc = idx & 63;
            Ps[rr][cc] = P[(size_t)(q0 + rr) * TN + k0 + cc];
            Vs[rr][cc] = qkv[((size_t)(b * TN + k0 + rr)) * 1536 + 1024 + h * 64 + cc];
        }
        __syncthreads();
        #pragma unroll 8
        for (int kk = 0; kk < 64; kk++) {
            float a0 = Ps[ty * 4 + 0][kk], a1 = Ps[ty * 4 + 1][kk], a2 = Ps[ty * 4 + 2][kk], a3 = Ps[ty * 4 + 3][kk];
            float b0 = Vs[kk][tx * 4 + 0], b1 = Vs[kk][tx * 4 + 1], b2 = Vs[kk][tx * 4 + 2], b3 = Vs[kk][tx * 4 + 3];
            acc[0][0] += a0 * b0; acc[0][1] += a0 * b1; acc[0][2] += a0 * b2; acc[0][3] += a0 * b3;
            acc[1][0] += a1 * b0; acc[1][1] += a1 * b1; acc[1][2] += a1 * b2; acc[1][3] += a1 * b3;
            acc[2][0] += a2 * b0; acc[2][1] += a2 * b1; acc[2][2] += a2 * b2; acc[2][3] += a2 * b3;
            acc[3][0] += a3 * b0; acc[3][1] += a3 * b1; acc[3][2] += a3 * b2; acc[3][3] += a3 * b3;
        }
        __syncthreads();
    }
    #pragma unroll
    for (int i = 0; i < 4; i++)
        #pragma unroll
        for (int j = 0; j < 4; j++)
            o[((size_t)(b * TN + q0 + ty * 4 + i)) * DM + h * 64 + tx * 4 + j] = acc[i][j];
}

// ---------------- launch ----------------
extern "C" void kernel_launch(void* const* d_in, const int* in_sizes, int n_in,
                              void* d_out, int out_size) {
    const int*   x      = (const int*)  d_in[0];
    const float* tok    = (const float*)d_in[1];
    const float* pos    = (const float*)d_in[2];
    const float* qkv_w  = (const float*)d_in[3];
    const float* qkv_b  = (const float*)d_in[4];
    const float* out_w  = (const float*)d_in[5];
    const float* out_b  = (const float*)d_in[6];
    const float* ln1_s  = (const float*)d_in[7];
    const float* ln1_b  = (const float*)d_in[8];
    const float* ff1_w  = (const float*)d_in[9];
    const float* ff1_b  = (const float*)d_in[10];
    const float* ff2_w  = (const float*)d_in[11];
    const float* ff2_b  = (const float*)d_in[12];
    const float* ln2_s  = (const float*)d_in[13];
    const float* ln2_b  = (const float*)d_in[14];
    const float* lnf_s  = (const float*)d_in[15];
    const float* lnf_b  = (const float*)d_in[16];
    const float* head_w = (const float*)d_in[17];
    const float* head_b = (const float*)d_in[18];
    float* out = (float*)d_out;

    float *h, *tmp, *qkv, *sc, *ff, *att;
    cudaGetSymbolAddress((void**)&h,   g_h);
    cudaGetSymbolAddress((void**)&tmp, g_tmp);
    cudaGetSymbolAddress((void**)&qkv, g_qkv);
    cudaGetSymbolAddress((void**)&sc,  g_sc);
    cudaGetSymbolAddress((void**)&ff,  g_ff);
    cudaGetSymbolAddress((void**)&att, g_att);

    const int M = BS * TN;  // 2048

    embed_k<<<(BS*TN*DM + 255) / 256, 256>>>(x, tok, pos, h);

    for (int l = 0; l < LN_; l++) {
        const float* w_qkv = qkv_w + (size_t)l * DM * 3 * DM;
        const float* b_qkv = qkv_b + (size_t)l * 3 * DM;
        const float* w_out = out_w + (size_t)l * DM * DM;
        const float* b_out = out_b + (size_t)l * DM;
        const float* w_f1  = ff1_w + (size_t)l * DM * 4 * DM;
        const float* b_f1  = ff1_b + (size_t)l * 4 * DM;
        const float* w_f2  = ff2_w + (size_t)l * 4 * DM * DM;
        const float* b_f2  = ff2_b + (size_t)l * DM;

        // attention block
        ln_k<<<M, 256>>>(h, tmp, ln1_s + l * DM, ln1_b + l * DM);
        gemm3<128,64,256,4,2,0,true><<<dim3(24, 16), 256>>>(tmp, w_qkv, b_qkv, nullptr, qkv, M, 3*DM, DM);
        scores_k<<<dim3(8, 8, 32), 256>>>(qkv, sc);
        softmax_k<<<(BS * HN * TN) / 8, 256>>>(sc);
        av_k<<<dim3(1, 8, 32), 256>>>(sc, qkv, att);
        gemm3<64,64,128,2,2,2,true><<<dim3(8, 32), 128>>>(att, w_out, b_out, h, h, M, DM, DM);

        // feed-forward block
        ln_k<<<M, 256>>>(h, tmp, ln2_s + l * DM, ln2_b + l * DM);
        gemm3<128,64,256,4,2,1,true><<<dim3(32, 16), 256>>>(tmp, w_f1, b_f1, nullptr, ff, M, 4*DM, DM);
        gemm3<64,64,128,2,2,2,true><<<dim3(8, 32), 128>>>(ff, w_f2, b_f2, h, h, M, DM, 4*DM);
    }

    // final LN + LM head (N = 50257 odd -> 4B cp.async with zero-fill)
    ln_k<<<M, 256>>>(h, tmp, lnf_s, lnf_b);
    gemm3<128,64,256,4,2,0,false><<<dim3((VN + 63) / 64, 16), 256>>>(tmp, head_w, head_b, nullptr, out, M, VN, DM);
}

// round 6
// speedup vs baseline: 2.2471x; 1.8153x over previous
#include <cuda_runtime.h>
#include <cuda_fp16.h>
#include <mma.h>
#include <cstdint>

using namespace nvcuda;

#define BS   4
#define TN   512
#define DM   512
#define HN   8
#define HDN  64
#define LN_  6
#define VN   50257
#define VNP  50304          // VN padded to multiple of 128
#define EPSV 1e-5f

// ---------------- scratch ----------------
__device__ float  g_h   [BS*TN*DM];          // residual stream (fp32)
__device__ float  g_qkv [BS*TN*3*DM];        // qkv activations (fp32, read by attention)
__device__ float  g_sc  [BS*HN*TN*TN];       // attention scores
__device__ __half g_tmpH[BS*TN*DM];          // LN output (fp16, GEMM A)
__device__ __half g_attH[BS*TN*DM];          // attention output (fp16, GEMM A)
__device__ __half g_ffH [BS*TN*4*DM];        // ff1 output (fp16, GEMM A)
// fp16 weights ([K,N] row-major, same layout as inputs)
__device__ __half g_qkvH[LN_*DM*3*DM];
__device__ __half g_outH[LN_*DM*DM];
__device__ __half g_ff1H[LN_*DM*4*DM];
__device__ __half g_ff2H[LN_*4*DM*DM];
__device__ __half g_headH[DM*VNP];           // padded with zeros

// ---------------- weight conversion ----------------
__global__ void convh_k(const float* __restrict__ src, __half* __restrict__ dst, int n) {
    int i = blockIdx.x * 256 + threadIdx.x;
    if (i < n) dst[i] = __float2half(src[i]);
}
__global__ void convpad_k(const float* __restrict__ src, __half* __restrict__ dst) {
    int n = blockIdx.x * 256 + threadIdx.x;
    int k = blockIdx.y;
    if (n < VNP)
        dst[(size_t)k * VNP + n] = (n < VN) ? __float2half(src[(size_t)k * VN + n]) : __half(0.0f);
}

// ---------------- embedding ----------------
__global__ void embed_k(const int* __restrict__ x, const float* __restrict__ tok,
                        const float* __restrict__ pos, float* __restrict__ h) {
    int i = blockIdx.x * 256 + threadIdx.x;
    if (i >= BS*TN*DM) return;
    int d  = i % DM;
    int bt = i / DM;
    int t  = bt % TN;
    h[i] = tok[(size_t)x[bt] * DM + d] + pos[t * DM + d];
}

// ---------------- layernorm: fp32 in -> fp16 out ----------------
__global__ __launch_bounds__(256) void ln_k(const float* __restrict__ in, __half* __restrict__ out,
                                            const float* __restrict__ sc, const float* __restrict__ bi) {
    __shared__ float s1[256], s2[256];
    int row = blockIdx.x;
    int tid = threadIdx.x;
    const float* xr = in + (size_t)row * DM;
    float a = xr[tid], b = xr[tid + 256];
    s1[tid] = a + b;
    s2[tid] = a * a + b * b;
    __syncthreads();
    for (int s = 128; s > 0; s >>= 1) {
        if (tid < s) { s1[tid] += s1[tid + s]; s2[tid] += s2[tid + s]; }
        __syncthreads();
    }
    float mean = s1[0] * (1.0f / DM);
    float var  = s2[0] * (1.0f / DM) - mean * mean;
    float r    = rsqrtf(var + EPSV);
    out[(size_t)row * DM + tid]       = __float2half((a - mean) * r * sc[tid]       + bi[tid]);
    out[(size_t)row * DM + tid + 256] = __float2half((b - mean) * r * sc[tid + 256] + bi[tid + 256]);
}

// ---------------- epilogue store helpers ----------------
__device__ __forceinline__ void stval(float* C, size_t i, float v)  { C[i] = v; }
__device__ __forceinline__ void stval(__half* C, size_t i, float v) { C[i] = __float2half(v); }

// ---------------- fp16 wmma GEMM, 2-stage cp.async ----------------
// C[M,N] = A[M,K](fp16) @ B[K,N](fp16) + bias (+epilogue), fp32 accumulate.
// MODE 0: bias; 1: bias + exact gelu; 2: bias + residual.
// Bs = B row stride (>= N, multiple of 8). All cp.async are 16B-aligned by construction.
template <int BN, int MODE, typename OT>
__global__ __launch_bounds__(256) void gemmh(const __half* __restrict__ A,
                                             const __half* __restrict__ B,
                                             const float* __restrict__ bias,
                                             const float* __restrict__ res,
                                             OT* __restrict__ C,
                                             int M, int N, int K, int Bs) {
    constexpr int BM  = 128;
    constexpr int BK  = 32;
    constexpr int LDA = 40;            // halves; 80B rows, 16B-aligned chunk bases
    constexpr int LDB = BN + 8;
    constexpr int FN  = BN / 32;       // b-frags per warp (warp tile 32 x BN/2)
    constexpr int CHB = BN / 8;        // 16B chunks per B row
    constexpr int IB  = (BK * CHB) / 256;

    __shared__ union SMU {
        struct { __half A[2][BM * LDA]; __half B[2][BK * LDB]; } p;
        float epi[8][16 * 20];
    } sm;

    const int tid  = threadIdx.x;
    const int warp = tid >> 5;
    const int lane = tid & 31;
    const int wm   = warp >> 1;        // 0..3
    const int wn   = warp & 1;         // 0..1
    const int m0   = blockIdx.x * BM;
    const int n0   = blockIdx.y * BN;

    const uint32_t sA0 = (uint32_t)__cvta_generic_to_shared(&sm.p.A[0][0]);
    const uint32_t sB0 = (uint32_t)__cvta_generic_to_shared(&sm.p.B[0][0]);

    wmma::fragment<wmma::accumulator, 16, 16, 16, float> acc[2][FN];
    #pragma unroll
    for (int i = 0; i < 2; i++)
        #pragma unroll
        for (int j = 0; j < FN; j++)
            wmma::fill_fragment(acc[i][j], 0.0f);

    auto issue = [&](int buf, int k0) {
        #pragma unroll
        for (int i = 0; i < 2; i++) {
            int idx = tid + i * 256;
            int r = idx >> 2, c = (idx & 3) * 8;
            uint32_t dst = sA0 + (uint32_t)(buf * BM * LDA + r * LDA + c) * 2u;
            const __half* src = A + (size_t)(m0 + r) * K + k0 + c;
            asm volatile("cp.async.cg.shared.global [%0], [%1], 16;" :: "r"(dst), "l"(src));
        }
        #pragma unroll
        for (int i = 0; i < IB; i++) {
            int idx = tid + i * 256;
            int r = idx / CHB, c = (idx % CHB) * 8;
            uint32_t dst = sB0 + (uint32_t)(buf * BK * LDB + r * LDB + c) * 2u;
            const __half* src = B + (size_t)(k0 + r) * Bs + n0 + c;
            asm volatile("cp.async.cg.shared.global [%0], [%1], 16;" :: "r"(dst), "l"(src));
        }
    };

    const int nst = K / BK;

    issue(0, 0);
    asm volatile("cp.async.commit_group;" ::: "memory");

    for (int s = 0; s < nst; s++) {
        if (s + 1 < nst) {
            issue((s + 1) & 1, (s + 1) * BK);
            asm volatile("cp.async.commit_group;" ::: "memory");
            asm volatile("cp.async.wait_group 1;" ::: "memory");
        } else {
            asm volatile("cp.async.wait_group 0;" ::: "memory");
        }
        __syncthreads();

        const int buf = s & 1;
        #pragma unroll
        for (int ks = 0; ks < BK; ks += 16) {
            wmma::fragment<wmma::matrix_a, 16, 16, 16, __half, wmma::row_major> af[2];
            wmma::fragment<wmma::matrix_b, 16, 16, 16, __half, wmma::row_major> bf[FN];
            #pragma unroll
            for (int i = 0; i < 2; i++)
                wmma::load_matrix_sync(af[i], &sm.p.A[buf][(wm * 32 + i * 16) * LDA + ks], LDA);
            #pragma unroll
            for (int j = 0; j < FN; j++)
                wmma::load_matrix_sync(bf[j], &sm.p.B[buf][ks * LDB + wn * (BN / 2) + j * 16], LDB);
            #pragma unroll
            for (int i = 0; i < 2; i++)
                #pragma unroll
                for (int j = 0; j < FN; j++)
                    wmma::mma_sync(acc[i][j], af[i], bf[j], acc[i][j]);
        }
        __syncthreads();
    }

    // fused epilogue via per-warp smem patch (pipeline smem is dead)
    float* patch = &sm.epi[warp][0];
    #pragma unroll
    for (int i = 0; i < 2; i++)
        #pragma unroll
        for (int j = 0; j < FN; j++) {
            wmma::store_matrix_sync(patch, acc[i][j], 20, wmma::mem_row_major);
            __syncwarp();
            const int rg0 = m0 + wm * 32 + i * 16;
            const int cg0 = n0 + wn * (BN / 2) + j * 16;
            #pragma unroll
            for (int e = 0; e < 8; e++) {
                int li  = lane * 8 + e;
                int r   = li >> 4;
                int c   = li & 15;
                int col = cg0 + c;
                if (col < N) {
                    size_t gi = (size_t)(rg0 + r) * N + col;
                    float v = patch[r * 20 + c] + bias[col];
                    if (MODE == 1) v = 0.5f * v * (1.0f + erff(v * 0.70710678118654752f));
                    if (MODE == 2) v += res[gi];
                    stval(C, gi, v);
                }
            }
            __syncwarp();
        }
}

// ---------------- attention: S = Q K^T * scale, causal (masked tiles not written) ----------------
__global__ __launch_bounds__(256) void scores_k(const float* __restrict__ qkv, float* __restrict__ sc) {
    int bh = blockIdx.z;
    int b  = bh >> 3;
    int h  = bh & 7;
    int q0 = blockIdx.y << 6;
    int j0 = blockIdx.x << 6;
    if (j0 > q0) return;   // fully masked tile: never read downstream
    float* out = sc + (size_t)bh * TN * TN;
    int tid = threadIdx.x;

    __shared__ float Qs[64][65], Ks[64][65];
    #pragma unroll
    for (int r = 0; r < 16; r++) {
        int idx = r * 256 + tid;
        int rr = idx >> 6, cc = idx & 63;
        Qs[rr][cc] = qkv[((size_t)(b * TN + q0 + rr)) * 1536 + h * 64 + cc];
        Ks[rr][cc] = qkv[((size_t)(b * TN + j0 + rr)) * 1536 + 512 + h * 64 + cc];
    }
    __syncthreads();

    int tx = tid & 15, ty = tid >> 4;
    float acc[4][4] = {};
    #pragma unroll 8
    for (int d = 0; d < 64; d++) {
        float a0 = Qs[ty * 4 + 0][d], a1 = Qs[ty * 4 + 1][d], a2 = Qs[ty * 4 + 2][d], a3 = Qs[ty * 4 + 3][d];
        float b0 = Ks[tx * 4 + 0][d], b1 = Ks[tx * 4 + 1][d], b2 = Ks[tx * 4 + 2][d], b3 = Ks[tx * 4 + 3][d];
        acc[0][0] += a0 * b0; acc[0][1] += a0 * b1; acc[0][2] += a0 * b2; acc[0][3] += a0 * b3;
        acc[1][0] += a1 * b0; acc[1][1] += a1 * b1; acc[1][2] += a1 * b2; acc[1][3] += a1 * b3;
        acc[2][0] += a2 * b0; acc[2][1] += a2 * b1; acc[2][2] += a2 * b2; acc[2][3] += a2 * b3;
        acc[3][0] += a3 * b0; acc[3][1] += a3 * b1; acc[3][2] += a3 * b2; acc[3][3] += a3 * b3;
    }
    #pragma unroll
    for (int i = 0; i < 4; i++)
        #pragma unroll
        for (int j = 0; j < 4; j++) {
            int row = q0 + ty * 4 + i;
            int col = j0 + tx * 4 + j;
            out[(size_t)row * TN + col] = (col <= row) ? acc[i][j] * 0.125f : -1e30f;
        }
}

// ---------------- softmax (causal: only reads/writes up to diagonal 64-tile) ----------------
__global__ __launch_bounds__(256) void softmax_k(float* __restrict__ sc) {
    int warp = threadIdx.x >> 5, lane = threadIdx.x & 31;
    size_t row = (size_t)blockIdx.x * 8 + warp;
    int r = (int)(row & (TN - 1));
    int imax = (((r >> 6) + 1) << 1);        // 32-col chunks up to diagonal tile end
    float* p = sc + row * TN;
    float v[16];
    float mx = -3.4e38f;
    #pragma unroll
    for (int i = 0; i < 16; i++) {
        v[i] = (i < imax) ? p[lane + 32 * i] : -3.4e38f;
        mx = fmaxf(mx, v[i]);
    }
    #pragma unroll
    for (int o = 16; o; o >>= 1) mx = fmaxf(mx, __shfl_xor_sync(0xffffffffu, mx, o));
    float s = 0.0f;
    #pragma unroll
    for (int i = 0; i < 16; i++) {
        v[i] = (i < imax) ? expf(v[i] - mx) : 0.0f;
        s += v[i];
    }
    #pragma unroll
    for (int o = 16; o; o >>= 1) s += __shfl_xor_sync(0xffffffffu, s, o);
    float inv = 1.0f / s;
    #pragma unroll
    for (int i = 0; i < 16; i++)
        if (i < imax) p[lane + 32 * i] = v[i] * inv;
}

// ---------------- O = P @ V  (fp16 output for proj GEMM) ----------------
__global__ __launch_bounds__(256) void av_k(const float* __restrict__ sc, const float* __restrict__ qkv,
                                            __half* __restrict__ o) {
    int bh = blockIdx.z;
    int b  = bh >> 3;
    int h  = bh & 7;
    int q0 = blockIdx.y << 6;
    const float* P = sc + (size_t)bh * TN * TN;

    __shared__ float Ps[64][65], Vs[64][65];
    int tid = threadIdx.x;
    int tx = tid & 15, ty = tid >> 4;
    float acc[4][4] = {};

    for (int k0 = 0; k0 <= q0; k0 += 64) {
        #pragma unroll
        for (int r = 0; r < 16; r++) {
            int idx = r * 256 + tid;
            int rr = idx >> 6, cc = idx & 63;
            Ps[rr][cc] = P[(size_t)(q0 + rr) * TN + k0 + cc];
            Vs[rr][cc] = qkv[((size_t)(b * TN + k0 + rr)) * 1536 + 1024 + h * 64 + cc];
        }
        __syncthreads();
        #pragma unroll 8
        for (int kk = 0; kk < 64; kk++) {
            float a0 = Ps[ty * 4 + 0][kk], a1 = Ps[ty * 4 + 1][kk], a2 = Ps[ty * 4 + 2][kk], a3 = Ps[ty * 4 + 3][kk];
            float b0 = Vs[kk][tx * 4 + 0], b1 = Vs[kk][tx * 4 + 1], b2 = Vs[kk][tx * 4 + 2], b3 = Vs[kk][tx * 4 + 3];
            acc[0][0] += a0 * b0; acc[0][1] += a0 * b1; acc[0][2] += a0 * b2; acc[0][3] += a0 * b3;
            acc[1][0] += a1 * b0; acc[1][1] += a1 * b1; acc[1][2] += a1 * b2; acc[1][3] += a1 * b3;
            acc[2][0] += a2 * b0; acc[2][1] += a2 * b1; acc[2][2] += a2 * b2; acc[2][3] += a2 * b3;
            acc[3][0] += a3 * b0; acc[3][1] += a3 * b1; acc[3][2] += a3 * b2; acc[3][3] += a3 * b3;
        }
        __syncthreads();
    }
    #pragma unroll
    for (int i = 0; i < 4; i++)
        #pragma unroll
        for (int j = 0; j < 4; j++)
            o[((size_t)(b * TN + q0 + ty * 4 + i)) * DM + h * 64 + tx * 4 + j] =
                __float2half(acc[i][j]);
}

// ---------------- launch ----------------
extern "C" void kernel_launch(void* const* d_in, const int* in_sizes, int n_in,
                              void* d_out, int out_size) {
    const int*   x      = (const int*)  d_in[0];
    const float* tok    = (const float*)d_in[1];
    const float* pos    = (const float*)d_in[2];
    const float* qkv_w  = (const float*)d_in[3];
    const float* qkv_b  = (const float*)d_in[4];
    const float* out_w  = (const float*)d_in[5];
    const float* out_b  = (const float*)d_in[6];
    const float* ln1_s  = (const float*)d_in[7];
    const float* ln1_b  = (const float*)d_in[8];
    const float* ff1_w  = (const float*)d_in[9];
    const float* ff1_b  = (const float*)d_in[10];
    const float* ff2_w  = (const float*)d_in[11];
    const float* ff2_b  = (const float*)d_in[12];
    const float* ln2_s  = (const float*)d_in[13];
    const float* ln2_b  = (const float*)d_in[14];
    const float* lnf_s  = (const float*)d_in[15];
    const float* lnf_b  = (const float*)d_in[16];
    const float* head_w = (const float*)d_in[17];
    const float* head_b = (const float*)d_in[18];
    float* out = (float*)d_out;

    float *h, *qkv, *sc;
    __half *tmpH, *attH, *ffH, *qkvH, *outH, *ff1H, *ff2H, *headH;
    cudaGetSymbolAddress((void**)&h,    g_h);
    cudaGetSymbolAddress((void**)&qkv,  g_qkv);
    cudaGetSymbolAddress((void**)&sc,   g_sc);
    cudaGetSymbolAddress((void**)&tmpH, g_tmpH);
    cudaGetSymbolAddress((void**)&attH, g_attH);
    cudaGetSymbolAddress((void**)&ffH,  g_ffH);
    cudaGetSymbolAddress((void**)&qkvH, g_qkvH);
    cudaGetSymbolAddress((void**)&outH, g_outH);
    cudaGetSymbolAddress((void**)&ff1H, g_ff1H);
    cudaGetSymbolAddress((void**)&ff2H, g_ff2H);
    cudaGetSymbolAddress((void**)&headH,g_headH);

    const int M = BS * TN;  // 2048

    // weight conversions (fp32 -> fp16)
    {
        int n;
        n = LN_*DM*3*DM;   convh_k<<<(n+255)/256, 256>>>(qkv_w, qkvH, n);
        n = LN_*DM*DM;     convh_k<<<(n+255)/256, 256>>>(out_w, outH, n);
        n = LN_*DM*4*DM;   convh_k<<<(n+255)/256, 256>>>(ff1_w, ff1H, n);
        n = LN_*4*DM*DM;   convh_k<<<(n+255)/256, 256>>>(ff2_w, ff2H, n);
        convpad_k<<<dim3((VNP+255)/256, DM), 256>>>(head_w, headH);
    }

    embed_k<<<(BS*TN*DM + 255) / 256, 256>>>(x, tok, pos, h);

    for (int l = 0; l < LN_; l++) {
        const __half* wq = qkvH + (size_t)l * DM * 3*DM;
        const __half* wo = outH + (size_t)l * DM * DM;
        const __half* w1 = ff1H + (size_t)l * DM * 4*DM;
        const __half* w2 = ff2H + (size_t)l * 4*DM * DM;
        const float* bq = qkv_b + (size_t)l * 3*DM;
        const float* bo = out_b + (size_t)l * DM;
        const float* b1 = ff1_b + (size_t)l * 4*DM;
        const float* b2 = ff2_b + (size_t)l * DM;

        // attention block
        ln_k<<<M, 256>>>(h, tmpH, ln1_s + l * DM, ln1_b + l * DM);
        gemmh<128,0,float><<<dim3(16, 12), 256>>>(tmpH, wq, bq, nullptr, qkv, M, 3*DM, DM, 3*DM);
        scores_k<<<dim3(8, 8, 32), 256>>>(qkv, sc);
        softmax_k<<<(BS * HN * TN) / 8, 256>>>(sc);
        av_k<<<dim3(1, 8, 32), 256>>>(sc, qkv, attH);
        gemmh<64,2,float><<<dim3(16, 8), 256>>>(attH, wo, bo, h, h, M, DM, DM, DM);

        // feed-forward block
        ln_k<<<M, 256>>>(h, tmpH, ln2_s + l * DM, ln2_b + l * DM);
        gemmh<128,1,__half><<<dim3(16, 16), 256>>>(tmpH, w1, b1, nullptr, ffH, M, 4*DM, DM, 4*DM);
        gemmh<64,2,float><<<dim3(16, 8), 256>>>(ffH, w2, b2, h, h, M, DM, 4*DM, DM);
    }

    // final LN + LM head (B padded to VNP: all loads 16B-aligned; C guarded by col < VN)
    ln_k<<<M, 256>>>(h, tmpH, lnf_s, lnf_b);
    gemmh<128,0,float><<<dim3(16, VNP / 128), 256>>>(tmpH, headH, head_b, nullptr, out, M, VN, DM, VNP);
}